// round 6
// baseline (speedup 1.0000x reference)
#include <cuda_runtime.h>
#include <cuda_bf16.h>
#include <math.h>

#define BB 4
#define LL 64
#define DD 64
#define RELN 16
#define NEGV (-1e9f)
#define LOSS_SCALE 4398046511104.0   // 2^42
#define NT 192

// ---------------- fast math helpers ------------------------------------------
__device__ __forceinline__ float rcpa(float x) {
    float y; asm("rcp.approx.f32 %0, %1;" : "=f"(y) : "f"(x)); return y;
}
__device__ __forceinline__ float sigm(float x)  { return rcpa(1.f + __expf(-x)); }
__device__ __forceinline__ float tanha(float x) { return 1.f - 2.f * rcpa(__expf(2.f * x) + 1.f); }

// ---------------- packed f32x2 FMA helpers ------------------------------------
__device__ __forceinline__ void fma2(unsigned long long& d,
                                     unsigned long long a, unsigned long long b) {
    asm("fma.rn.f32x2 %0, %1, %2, %0;" : "+l"(d) : "l"(a), "l"(b));
}
__device__ __forceinline__ void unpack2(unsigned long long v, float& x, float& y) {
    asm("mov.b64 {%0,%1}, %2;" : "=f"(x), "=f"(y) : "l"(v));
}
__device__ __forceinline__ float dot64(const ulonglong2* __restrict__ a,
                                       const ulonglong2* __restrict__ b) {
    unsigned long long a0 = 0ULL, a1 = 0ULL, a2 = 0ULL, a3 = 0ULL;
#pragma unroll
    for (int q = 0; q < 16; q += 2) {
        ulonglong2 x = a[q], y = b[q];
        ulonglong2 x2 = a[q + 1], y2 = b[q + 1];
        fma2(a0, x.x, y.x);  fma2(a1, x.y, y.y);
        fma2(a2, x2.x, y2.x); fma2(a3, x2.y, y2.y);
    }
    float s0, s1, s2, s3, s4, s5, s6, s7;
    unpack2(a0, s0, s1); unpack2(a1, s2, s3);
    unpack2(a2, s4, s5); unpack2(a3, s6, s7);
    return ((s0 + s1) + (s2 + s3)) + ((s4 + s5) + (s6 + s7));
}

// ---------------- global scratch & sync ---------------------------------------
__device__ __align__(16) float g_o[BB * LL * DD];
__device__ __align__(16) float g_s[BB * RELN * LL * LL];
__device__ __align__(16) float g_gx[BB * LL * 3 * DD];
__device__ unsigned long long g_lossint;
__device__ unsigned int g_pA, g_pB, g_loss;   // zero-init; finisher resets each launch

struct PA { float so[LL * DD]; float sv[16 * DD]; };
struct PB { float sob[LL][DD + 1]; float sp[LL]; float sctx[DD]; float so2[DD]; float wred[4]; };
struct PC {
    float shseq[LL][DD];
    float sh[DD]; float sgh[3 * DD];
    float sga[LL][3]; float sa[LL]; float sw[LL];
    float sc[DD]; float sh1[DD / 2]; float slog[2]; float wred[4];
    int smaxl;
};
union SmemU { PA a; PB b; PC c; };

__global__ void __launch_bounds__(NT)
mega(const int* __restrict__ x, const int* __restrict__ yv,
     const int* __restrict__ r, const int* __restrict__ lv,
     const float* __restrict__ emb, const float* __restrict__ rel,
     const float* __restrict__ attW, const float* __restrict__ attb,
     const float* __restrict__ gWih, const float* __restrict__ Whh,
     const float* __restrict__ gbih, const float* __restrict__ bhh,
     const float* __restrict__ oWih, const float* __restrict__ oWhh,
     const float* __restrict__ obih, const float* __restrict__ obhh,
     const float* __restrict__ W1, const float* __restrict__ b1,
     const float* __restrict__ W2, const float* __restrict__ b2,
     float* __restrict__ out, int out_size) {
    __shared__ __align__(16) SmemU smem;
    int blk = blockIdx.x;     // 256
    int tid = threadIdx.x;    // 192

    // ========== Phase A: S_k score maps. blk -> (b, k, quarter) =============
    {
        int b = blk >> 6;
        int k = (blk >> 2) & 15;
        int q4 = blk & 3;
        float* so = smem.a.so;
        float* sv = smem.a.sv;

        for (int idx = tid; idx < LL * DD; idx += NT) {
            int l = idx >> 6, d = idx & 63;
            so[idx] = emb[x[b * LL + l] * DD + d];
        }
        __syncthreads();
        if (k == 0 && q4 == 0) {
            for (int idx = tid; idx < LL * DD; idx += NT) g_o[b * LL * DD + idx] = so[idx];
        }

        if (tid < 128) {                        // V-part
            int d    = tid & 63;
            int jgrp = tid >> 6;                // 0..1
            ulonglong2 m[16];
            const ulonglong2* mrow =
                reinterpret_cast<const ulonglong2*>(rel + (k * DD + d) * DD);
#pragma unroll
            for (int qq = 0; qq < 16; qq++) m[qq] = mrow[qq];
#pragma unroll
            for (int jj = 0; jj < 8; jj++) {
                int jl = jgrp * 8 + jj;
                int j  = q4 * 16 + jl;
                sv[jl * DD + d] =
                    dot64(m, reinterpret_cast<const ulonglong2*>(so + j * DD));
            }
        }
        __syncthreads();
        if (tid < 128) {                        // S-part
            int i    = tid & 63;
            int jgrp = tid >> 6;
            const ulonglong2* oi = reinterpret_cast<const ulonglong2*>(so + i * DD);
            float res[8];
#pragma unroll
            for (int jj = 0; jj < 8; jj++) {
                int jl = jgrp * 8 + jj;
                res[jj] = dot64(oi, reinterpret_cast<const ulonglong2*>(sv + jl * DD));
            }
            float4* dst = reinterpret_cast<float4*>(
                g_s + (((b * RELN + k) * LL + i) * LL) + q4 * 16 + jgrp * 8);
            dst[0] = make_float4(res[0], res[1], res[2], res[3]);
            dst[1] = make_float4(res[4], res[5], res[6], res[7]);
        }
        __syncthreads();
        if (tid == 0) { __threadfence(); atomicAdd(&g_pA, 1u); }
    }

    if (tid == 0) { while (*(volatile unsigned int*)&g_pA < 256u) __nanosleep(64); }
    __syncthreads();
    __threadfence();

    // ========== Phase B: softmax + context + projections. blk -> (b, i) =====
    {
        int b = blk >> 6;
        int i = blk & 63;
        PB& S = smem.b;

        const float* ob = g_o + b * LL * DD;
        for (int idx = tid; idx < LL * DD; idx += NT)
            S.sob[idx >> 6][idx & 63] = ob[idx];
        __syncthreads();

        if (tid < DD) {
            int j = tid;
            int rj = r[(b * LL + i) * LL + j];
            float s = (rj > 0) ? g_s[(((b * RELN + rj) * LL + i) * LL) + j] : NEGV;
            float mx = s;
#pragma unroll
            for (int off = 16; off; off >>= 1)
                mx = fmaxf(mx, __shfl_xor_sync(0xFFFFFFFFu, mx, off));
            if ((tid & 31) == 0) S.wred[tid >> 5] = mx;
            S.sp[j] = s;
        }
        __syncthreads();
        if (tid < DD) {
            float mx = fmaxf(S.wred[0], S.wred[1]);
            float e = __expf(S.sp[tid] - mx);
            float ss = e;
#pragma unroll
            for (int off = 16; off; off >>= 1) ss += __shfl_xor_sync(0xFFFFFFFFu, ss, off);
            if ((tid & 31) == 0) S.wred[2 + (tid >> 5)] = ss;
            S.sp[tid] = e;
        }
        __syncthreads();
        if (tid < DD) {
            float inv = rcpa(S.wred[2] + S.wred[3]);
            float acc = 0.f;
#pragma unroll 8
            for (int jj = 0; jj < LL; jj++) acc += S.sp[jj] * S.sob[jj][tid];
            S.sctx[tid] = acc * inv;
        }
        __syncthreads();
        if (tid < DD) {
            S.so2[tid] = attb[tid] +
                dot64(reinterpret_cast<const ulonglong2*>(attW + tid * DD),
                      reinterpret_cast<const ulonglong2*>(S.sctx));
        }
        __syncthreads();
        // gx projection: one row per thread (192 rows exactly)
        g_gx[(b * LL + i) * (3 * DD) + tid] = gbih[tid] +
            dot64(reinterpret_cast<const ulonglong2*>(gWih + tid * DD),
                  reinterpret_cast<const ulonglong2*>(S.so2));
        __syncthreads();
        if (tid == 0) { __threadfence(); atomicAdd(&g_pB, 1u); }
    }

    if (blk >= BB) return;

    if (tid == 0) { while (*(volatile unsigned int*)&g_pB < 256u) __nanosleep(64); }
    __syncthreads();
    __threadfence();

    // ========== Phase C: GRU + out-GRU + classifier. blocks 0..3 ============
    {
        int b = blk;
        int k = tid;              // 0..191, one Whh row each
        PC& C = smem.c;

        ulonglong2 w[16];         // 64 registers — fits, no spill
        const ulonglong2* wr = reinterpret_cast<const ulonglong2*>(Whh + k * DD);
#pragma unroll
        for (int qq = 0; qq < 16; qq++) w[qq] = wr[qq];
        float bk = bhh[k];

        if (k < DD) C.sh[k] = 0.f;
        if (k == 0) {
            int m = lv[0];
#pragma unroll
            for (int i = 1; i < BB; i++) m = max(m, lv[i]);
            C.smaxl = m + 1;
        }
        __syncthreads();

        const float* gxb = g_gx + b * LL * (3 * DD);
        float xr = 0.f, xz = 0.f, xn = 0.f;
        if (k < DD) { xr = gxb[k]; xz = gxb[DD + k]; xn = gxb[2 * DD + k]; }

        for (int l = 0; l < LL; l++) {
            // matvec row k against current h (stream h from shared)
            const ulonglong2* h2 = reinterpret_cast<const ulonglong2*>(C.sh);
            unsigned long long a0 = 0ULL, a1 = 0ULL, a2 = 0ULL, a3 = 0ULL;
#pragma unroll
            for (int qq = 0; qq < 16; qq += 2) {
                ulonglong2 hA = h2[qq], hB = h2[qq + 1];
                fma2(a0, w[qq].x, hA.x);     fma2(a1, w[qq].y, hA.y);
                fma2(a2, w[qq + 1].x, hB.x); fma2(a3, w[qq + 1].y, hB.y);
            }
            float s0, s1, s2, s3, s4, s5, s6, s7;
            unpack2(a0, s0, s1); unpack2(a1, s2, s3);
            unpack2(a2, s4, s5); unpack2(a3, s6, s7);
            C.sgh[k] = bk + ((s0 + s1) + (s2 + s3)) + ((s4 + s5) + (s6 + s7));
            __syncthreads();
            if (k < DD) {
                float rg = sigm(xr + C.sgh[k]);
                float zg = sigm(xz + C.sgh[DD + k]);
                float ng = tanha(xn + rg * C.sgh[2 * DD + k]);
                float hnew = (1.f - zg) * ng + zg * C.sh[k];
                C.sh[k] = hnew;
                C.shseq[l][k] = hnew;
                if (l + 1 < LL) {
                    const float* nx = gxb + (l + 1) * 3 * DD;
                    xr = nx[k]; xz = nx[DD + k]; xn = nx[2 * DD + k];
                }
            }
            __syncthreads();
        }

        // out-GRU input projections: 192 dots, one per thread
        {
            int l = k & 63, g = k >> 6;    // g 0..2
            C.sga[l][g] = obih[g] +
                dot64(reinterpret_cast<const ulonglong2*>(C.shseq[l]),
                      reinterpret_cast<const ulonglong2*>(oWih + g * DD));
        }
        __syncthreads();

        if (k == 0) {
            float h = 0.f;
            float w0 = oWhh[0], w1 = oWhh[1], wn = oWhh[2];
            float c0 = obhh[0], c1 = obhh[1], cn = obhh[2];
            for (int l = 0; l < LL; l++) {
                float rg = sigm(C.sga[l][0] + h * w0 + c0);
                float zg = sigm(C.sga[l][1] + h * w1 + c1);
                float ng = tanha(C.sga[l][2] + rg * (h * wn + cn));
                h = (1.f - zg) * ng + zg * h;
                C.sa[l] = h;
            }
        }
        __syncthreads();

        if (k < DD) {
            float v = (k < C.smaxl) ? C.sa[k] : NEGV;
            float mx = v;
#pragma unroll
            for (int off = 16; off; off >>= 1)
                mx = fmaxf(mx, __shfl_xor_sync(0xFFFFFFFFu, mx, off));
            if ((k & 31) == 0) C.wred[k >> 5] = mx;
            C.sa[k] = v;
        }
        __syncthreads();
        if (k < DD) {
            float mx = fmaxf(C.wred[0], C.wred[1]);
            float e = __expf(C.sa[k] - mx);
            float ss = e;
#pragma unroll
            for (int off = 16; off; off >>= 1) ss += __shfl_xor_sync(0xFFFFFFFFu, ss, off);
            if ((k & 31) == 0) C.wred[2 + (k >> 5)] = ss;
            C.sw[k] = e;
        }
        __syncthreads();
        if (k < DD) {
            float inv = rcpa(C.wred[2] + C.wred[3]);
            float acc = 0.f;
#pragma unroll 8
            for (int l = 0; l < LL; l++) acc += C.sw[l] * C.shseq[l][k];
            C.sc[k] = acc * inv;
        }
        __syncthreads();
        if (k < 32) {
            float acc = b1[k] +
                dot64(reinterpret_cast<const ulonglong2*>(W1 + k * DD),
                      reinterpret_cast<const ulonglong2*>(C.sc));
            C.sh1[k] = fmaxf(acc, 0.f);
        }
        __syncthreads();
        if (k < 2) {
            const float* wr2 = W2 + k * 32;
            float acc = b2[k];
#pragma unroll
            for (int m = 0; m < 32; m++) acc += C.sh1[m] * wr2[m];
            C.slog[k] = acc;
        }
        __syncthreads();

        if (k == 0) {
            float a0 = C.slog[0], a1 = C.slog[1];
            float mx = fmaxf(a0, a1);
            float e0 = __expf(a0 - mx), e1 = __expf(a1 - mx);
            float z = e0 + e1;
            float invz = rcpa(z);
            if (2 * b < out_size)     out[2 * b]     = e0 * invz;
            if (2 * b + 1 < out_size) out[2 * b + 1] = e1 * invz;
            float chosen = (yv[b] == 0) ? a0 : a1;
            float t = -(chosen - mx - __logf(z));
            atomicAdd(&g_lossint, (unsigned long long)((double)t * LOSS_SCALE));
            __threadfence();
            unsigned int c = atomicAdd(&g_loss, 1u);
            if (c == 3u) {
                unsigned long long s = atomicAdd(&g_lossint, 0ULL);
                if (out_size > 8)
                    out[8] = (float)((double)s * (1.0 / (4.0 * LOSS_SCALE)));
                for (int i = 9; i < out_size; i++) out[i] = 0.f;
                g_loss = 0u; g_pA = 0u; g_pB = 0u; g_lossint = 0ULL;
                __threadfence();
            }
        }
    }
}

// ---------------- launch ------------------------------------------------------
extern "C" void kernel_launch(void* const* d_in, const int* in_sizes, int n_in,
                              void* d_out, int out_size) {
    const int*   x    = (const int*)  d_in[0];
    const int*   y    = (const int*)  d_in[1];
    const int*   r    = (const int*)  d_in[2];
    const int*   l    = (const int*)  d_in[3];
    const float* emb  = (const float*)d_in[4];
    const float* rel  = (const float*)d_in[5];
    const float* attW = (const float*)d_in[6];
    const float* attb = (const float*)d_in[7];
    const float* gWih = (const float*)d_in[8];
    const float* gWhh = (const float*)d_in[9];
    const float* gbih = (const float*)d_in[10];
    const float* gbhh = (const float*)d_in[11];
    const float* oWih = (const float*)d_in[12];
    const float* oWhh = (const float*)d_in[13];
    const float* obih = (const float*)d_in[14];
    const float* obhh = (const float*)d_in[15];
    const float* W1   = (const float*)d_in[16];
    const float* b1   = (const float*)d_in[17];
    const float* W2   = (const float*)d_in[18];
    const float* b2   = (const float*)d_in[19];

    mega<<<256, NT>>>(x, y, r, l, emb, rel, attW, attb,
                      gWih, gWhh, gbih, gbhh,
                      oWih, oWhh, obih, obhh,
                      W1, b1, W2, b2, (float*)d_out, out_size);
}